// round 2
// baseline (speedup 1.0000x reference)
#include <cuda_runtime.h>

#define B_   4
#define N_   4096
#define DIN  128
#define DH   64
#define DO   128
#define TM   128
#define TN   128
#define SP_STRIDE (TN + 4)
#define NEG_BIG (-9.0e15f)
#define NW   (N_/32)

// ---------------- scratch (static device allocations are allowed) ----------------
__device__ float    g_Whs[B_*N_*DH];      // 4 MB
__device__ float    g_Wht[B_*N_*DH];      // 4 MB
__device__ float    g_Whc[B_*N_*DO];      // 8 MB
__device__ unsigned g_adjbits[N_*NW];     // 2 MB

// ---------------- packed fp32 FMA (Blackwell f32x2, 2x FFMA throughput) ----------
__device__ __forceinline__ float2 ffma2(float2 a, float2 b, float2 c) {
    unsigned long long ua = *reinterpret_cast<unsigned long long*>(&a);
    unsigned long long ub = *reinterpret_cast<unsigned long long*>(&b);
    unsigned long long uc = *reinterpret_cast<unsigned long long*>(&c);
    unsigned long long ud;
    asm("fma.rn.f32x2 %0, %1, %2, %3;" : "=l"(ud) : "l"(ua), "l"(ub), "l"(uc));
    return *reinterpret_cast<float2*>(&ud);
}

// ---------------- kernel 1: projections h@Ws, h@Wt, h@Wc -------------------------
// block = 256 threads, 16 rows of h per block. shT is [k][r] so we can use packed
// row-pair accumulation.
__global__ void gat_proj_kernel(const float* __restrict__ h,
                                const float* __restrict__ Ws,
                                const float* __restrict__ Wt,
                                const float* __restrict__ Wc) {
    __shared__ float shT[DIN*16];     // transposed: [k][r]
    const int r0 = blockIdx.x * 16;

    for (int idx = threadIdx.x; idx < 16*(DIN/4); idx += 256) {
        int k4 = idx >> 4;
        int r  = idx & 15;
        float4 v = *(const float4*)(h + (size_t)(r0 + r)*DIN + k4*4);
        shT[(k4*4+0)*16 + r] = v.x;
        shT[(k4*4+1)*16 + r] = v.y;
        shT[(k4*4+2)*16 + r] = v.z;
        shT[(k4*4+3)*16 + r] = v.w;
    }
    __syncthreads();

    const int t = threadIdx.x;
    const float* Wp; int stride, c, ostride; float* outp;
    if (t < 64)       { Wp = Ws; stride = DH; c = t;       outp = g_Whs; ostride = DH; }
    else if (t < 128) { Wp = Wt; stride = DH; c = t - 64;  outp = g_Wht; ostride = DH; }
    else              { Wp = Wc; stride = DO; c = t - 128; outp = g_Whc; ostride = DO; }

    float2 acc[8];
#pragma unroll
    for (int q = 0; q < 8; q++) acc[q] = make_float2(0.f, 0.f);

#pragma unroll 4
    for (int k = 0; k < DIN; k++) {
        float  w  = Wp[k*stride + c];
        float2 wp = make_float2(w, w);
        const float2* hp = (const float2*)(shT + k*16);
#pragma unroll
        for (int q = 0; q < 8; q++) acc[q] = ffma2(wp, hp[q], acc[q]);
    }
#pragma unroll
    for (int q = 0; q < 8; q++) {
        outp[(size_t)(r0 + 2*q    )*ostride + c] = acc[q].x;
        outp[(size_t)(r0 + 2*q + 1)*ostride + c] = acc[q].y;
    }
}

// ---------------- kernel 2: pack adjacency into bitmask --------------------------
__global__ void gat_pack_adj_kernel(const int* __restrict__ adj) {
    const int row  = blockIdx.x;
    const int wi   = threadIdx.x >> 5;
    const int lane = threadIdx.x & 31;
#pragma unroll 4
    for (int w = 0; w < 32; w++) {
        int word = wi*32 + w;
        int col  = word*32 + lane;
        unsigned bit = (adj[(size_t)row*N_ + col] > 0) ? 1u : 0u;
        unsigned m = __ballot_sync(0xffffffffu, bit);
        if (lane == 0) g_adjbits[row*NW + word] = m;
    }
}

// ---------------- kernel 3: fused masked-softmax attention (flash style) ---------
// grid (N/TM, B), 256 threads = 16x16, 8x8 micro-tiles, packed f32x2 FMAs.
__global__ void __launch_bounds__(256, 1)
gat_attn_kernel(float* __restrict__ out) {
    extern __shared__ float smem[];
    float* sQ  = smem;                 // TM x DH   (row-major)
    float* sKT = sQ  + TM*DH;          // DH x TN   (k-major, keys contiguous)
    float* sV  = sKT + DH*TN;          // TN x DO   (row-major)
    float* sP  = sV  + TN*DO;          // TM x SP_STRIDE

    const int b    = blockIdx.y;
    const int row0 = blockIdx.x * TM;
    const int tid  = threadIdx.x;
    const int tx   = tid & 15;
    const int ty   = tid >> 4;
    const int ty8  = ty * 8;
    const int tx8  = tx * 8;

    const float* Whs = g_Whs + (size_t)b*N_*DH;
    const float* Wht = g_Wht + (size_t)b*N_*DH;
    const float* Whc = g_Whc + (size_t)b*N_*DO;

    // Q tile (contiguous copy)
    {
        const float4* src = (const float4*)(Whs + (size_t)row0*DH);
        float4* dst = (float4*)sQ;
        for (int idx = tid; idx < TM*DH/4; idx += 256) dst[idx] = src[idx];
    }

    float2 o2[8][4];
#pragma unroll
    for (int i = 0; i < 8; i++)
#pragma unroll
        for (int jp = 0; jp < 4; jp++) o2[i][jp] = make_float2(0.f, 0.f);
    float mrow[8], lrow[8];
#pragma unroll
    for (int i = 0; i < 8; i++) { mrow[i] = -3.0e38f; lrow[i] = 0.f; }

    for (int kt = 0; kt < N_/TN; kt++) {
        const int key0 = kt * TN;
        __syncthreads();   // protect smem from previous iteration's readers

        // load K tile transposed: sKT[k][key]
        for (int idx = tid; idx < TN*(DH/4); idx += 256) {
            int k4  = idx >> 7;          // 0..15
            int key = idx & (TN - 1);    // 0..127
            float4 v = *(const float4*)(Wht + (size_t)(key0 + key)*DH + k4*4);
            sKT[(k4*4+0)*TN + key] = v.x;
            sKT[(k4*4+1)*TN + key] = v.y;
            sKT[(k4*4+2)*TN + key] = v.z;
            sKT[(k4*4+3)*TN + key] = v.w;
        }
        // load V tile (contiguous)
        {
            const float4* src = (const float4*)(Whc + (size_t)key0*DO);
            float4* dst = (float4*)sV;
            for (int idx = tid; idx < TN*DO/4; idx += 256) dst[idx] = src[idx];
        }
        __syncthreads();

        // ---- S = Q @ K^T (128x128 tile, fp32, packed) ----
        float2 s2[8][4];
#pragma unroll
        for (int i = 0; i < 8; i++)
#pragma unroll
            for (int jp = 0; jp < 4; jp++) s2[i][jp] = make_float2(0.f, 0.f);

#pragma unroll 4
        for (int k4 = 0; k4 < DH/4; k4++) {
            float4 a4[8];
#pragma unroll
            for (int i = 0; i < 8; i++)
                a4[i] = *(const float4*)(sQ + (ty8 + i)*DH + k4*4);
#pragma unroll
            for (int kk = 0; kk < 4; kk++) {
                const float* bp = sKT + (k4*4 + kk)*TN + tx8;
                float4 b0 = *(const float4*)bp;
                float4 b1 = *(const float4*)(bp + 4);
                float2 bb[4];
                bb[0] = make_float2(b0.x, b0.y); bb[1] = make_float2(b0.z, b0.w);
                bb[2] = make_float2(b1.x, b1.y); bb[3] = make_float2(b1.z, b1.w);
#pragma unroll
                for (int i = 0; i < 8; i++) {
                    float av = (kk == 0) ? a4[i].x : (kk == 1) ? a4[i].y
                             : (kk == 2) ? a4[i].z : a4[i].w;
                    float2 ap = make_float2(av, av);
#pragma unroll
                    for (int jp = 0; jp < 4; jp++)
                        s2[i][jp] = ffma2(ap, bb[jp], s2[i][jp]);
                }
            }
        }

        // ---- mask + online softmax update ----
#pragma unroll
        for (int i = 0; i < 8; i++) {
            const int grow = row0 + ty8 + i;
            unsigned wbits = g_adjbits[grow*NW + (key0 >> 5) + (tx >> 2)];
            unsigned bits8 = wbits >> ((tx & 3) * 8);
#pragma unroll
            for (int jp = 0; jp < 4; jp++) {
                if (!((bits8 >> (2*jp    )) & 1u)) s2[i][jp].x = NEG_BIG;
                if (!((bits8 >> (2*jp + 1)) & 1u)) s2[i][jp].y = NEG_BIG;
            }
            float tm = fmaxf(fmaxf(fmaxf(s2[i][0].x, s2[i][0].y),
                                   fmaxf(s2[i][1].x, s2[i][1].y)),
                             fmaxf(fmaxf(s2[i][2].x, s2[i][2].y),
                                   fmaxf(s2[i][3].x, s2[i][3].y)));
#pragma unroll
            for (int off = 1; off < 16; off <<= 1)
                tm = fmaxf(tm, __shfl_xor_sync(0xffffffffu, tm, off));
            float mold  = mrow[i];
            float mnew  = fmaxf(mold, tm);
            float scale = __expf(mold - mnew);
            mrow[i] = mnew;
            float rs = 0.f;
#pragma unroll
            for (int jp = 0; jp < 4; jp++) {
                float px = __expf(s2[i][jp].x - mnew);
                float py = __expf(s2[i][jp].y - mnew);
                s2[i][jp].x = px; s2[i][jp].y = py;
                rs += px + py;
            }
#pragma unroll
            for (int off = 1; off < 16; off <<= 1)
                rs += __shfl_xor_sync(0xffffffffu, rs, off);
            lrow[i] = lrow[i]*scale + rs;
#pragma unroll
            for (int jp = 0; jp < 4; jp++) { o2[i][jp].x *= scale; o2[i][jp].y *= scale; }

            float4 p0 = make_float4(s2[i][0].x, s2[i][0].y, s2[i][1].x, s2[i][1].y);
            float4 p1 = make_float4(s2[i][2].x, s2[i][2].y, s2[i][3].x, s2[i][3].y);
            *(float4*)(sP + (ty8 + i)*SP_STRIDE + tx8    ) = p0;
            *(float4*)(sP + (ty8 + i)*SP_STRIDE + tx8 + 4) = p1;
        }
        __syncthreads();

        // ---- O += P @ V (128 keys x 128 out cols) ----
#pragma unroll 2
        for (int k4 = 0; k4 < TN/4; k4++) {
            float4 a4[8];
#pragma unroll
            for (int i = 0; i < 8; i++)
                a4[i] = *(const float4*)(sP + (ty8 + i)*SP_STRIDE + k4*4);
#pragma unroll
            for (int kk = 0; kk < 4; kk++) {
                const float* bp = sV + (k4*4 + kk)*DO + tx8;
                float4 b0 = *(const float4*)bp;
                float4 b1 = *(const float4*)(bp + 4);
                float2 bb[4];
                bb[0] = make_float2(b0.x, b0.y); bb[1] = make_float2(b0.z, b0.w);
                bb[2] = make_float2(b1.x, b1.y); bb[3] = make_float2(b1.z, b1.w);
#pragma unroll
                for (int i = 0; i < 8; i++) {
                    float av = (kk == 0) ? a4[i].x : (kk == 1) ? a4[i].y
                             : (kk == 2) ? a4[i].z : a4[i].w;
                    float2 ap = make_float2(av, av);
#pragma unroll
                    for (int jp = 0; jp < 4; jp++)
                        o2[i][jp] = ffma2(ap, bb[jp], o2[i][jp]);
                }
            }
        }
    }

    // ---- epilogue: normalize and store ----
#pragma unroll
    for (int i = 0; i < 8; i++) {
        float inv = 1.f / lrow[i];
        const int grow = row0 + ty8 + i;
        float4 r0v = make_float4(o2[i][0].x*inv, o2[i][0].y*inv,
                                 o2[i][1].x*inv, o2[i][1].y*inv);
        float4 r1v = make_float4(o2[i][2].x*inv, o2[i][2].y*inv,
                                 o2[i][3].x*inv, o2[i][3].y*inv);
        float4* op = (float4*)(out + ((size_t)b*N_ + grow)*DO + tx8);
        op[0] = r0v;
        op[1] = r1v;
    }
}

// ---------------- launch ----------------------------------------------------------
extern "C" void kernel_launch(void* const* d_in, const int* in_sizes, int n_in,
                              void* d_out, int out_size) {
    const float* h   = (const float*)d_in[0];
    const int*   adj = (const int*)  d_in[1];
    const float* Ws  = (const float*)d_in[2];
    const float* Wt  = (const float*)d_in[3];
    const float* Wc  = (const float*)d_in[4];
    float* out = (float*)d_out;

    const int smem_bytes = (TM*DH + DH*TN + TN*DO + TM*SP_STRIDE) * sizeof(float);
    cudaFuncSetAttribute(gat_attn_kernel,
                         cudaFuncAttributeMaxDynamicSharedMemorySize, smem_bytes);

    gat_proj_kernel<<<B_*N_/16, 256>>>(h, Ws, Wt, Wc);
    gat_pack_adj_kernel<<<N_, 128>>>(adj);
    gat_attn_kernel<<<dim3(N_/TM, B_), 256, smem_bytes>>>(out);
}

// round 5
// speedup vs baseline: 2.7467x; 2.7467x over previous
#include <cuda_runtime.h>

#define B_   4
#define N_   4096
#define DIN  128
#define DH   64
#define DO   128
#define TM   128
#define TN   128
#define NT   (N_/TN)       // 32
#define NW   (N_/32)       // 128 mask words per row
#define LOG2E 1.4426950408889634f
#define EXPC  92.33248261689366f   /* 64 * log2(e) */

// ---------------- scratch ----------------
__device__ float    g_Whs[B_*N_*DH];
__device__ float    g_Wht[B_*N_*DH];
__device__ float    g_Whc[B_*N_*DO];
__device__ __align__(16) unsigned g_adjbits[N_*NW];
// pre-split, pre-swizzled bf16 images. Q/K: per (b,t) 128x64 bf16 (16KB).
// V: per (b,t) transposed 128(dout)x128(key) bf16 (32KB), 256B rows.
__device__ __align__(16) unsigned short g_Q1[B_*NT*8192];
__device__ __align__(16) unsigned short g_Q2[B_*NT*8192];
__device__ __align__(16) unsigned short g_K1[B_*NT*8192];
__device__ __align__(16) unsigned short g_K2[B_*NT*8192];
__device__ __align__(16) unsigned short g_V1[B_*NT*16384];
__device__ __align__(16) unsigned short g_V2[B_*NT*16384];

// ---------------- helpers ----------------
__device__ __forceinline__ unsigned smem_u32(const void* p) {
    unsigned a;
    asm("{ .reg .u64 t; cvta.to.shared.u64 t, %1; cvt.u32.u64 %0, t; }" : "=r"(a) : "l"(p));
    return a;
}
__device__ __forceinline__ float ex2f(float x) {
    float r; asm("ex2.approx.ftz.f32 %0, %1;" : "=f"(r) : "f"(x)); return r;
}
// split (a,b) into bf16x2 hi-part w1 and bf16x2 residual w2 (lo=a, hi=b)
__device__ __forceinline__ void split2(float a, float b, unsigned &w1, unsigned &w2) {
    unsigned hb;
    asm("cvt.rn.bf16x2.f32 %0, %1, %2;" : "=r"(hb) : "f"(b), "f"(a));
    float fa = __uint_as_float(hb << 16);
    float fb = __uint_as_float(hb & 0xffff0000u);
    asm("cvt.rn.bf16x2.f32 %0, %1, %2;" : "=r"(w2) : "f"(b - fb), "f"(a - fa));
    w1 = hb;
}
__device__ __forceinline__ float2 ffma2(float2 a, float2 b, float2 c) {
    unsigned long long ua = *reinterpret_cast<unsigned long long*>(&a);
    unsigned long long ub = *reinterpret_cast<unsigned long long*>(&b);
    unsigned long long uc = *reinterpret_cast<unsigned long long*>(&c);
    unsigned long long ud;
    asm("fma.rn.f32x2 %0, %1, %2, %3;" : "=l"(ud) : "l"(ua), "l"(ub), "l"(uc));
    return *reinterpret_cast<float2*>(&ud);
}
__device__ __forceinline__ void ldsm4(unsigned* r, unsigned addr) {
    asm volatile("ldmatrix.sync.aligned.m8n8.x4.shared.b16 {%0,%1,%2,%3}, [%4];"
        : "=r"(r[0]), "=r"(r[1]), "=r"(r[2]), "=r"(r[3]) : "r"(addr));
}
__device__ __forceinline__ void mma16816(float* c, unsigned a0, unsigned a1,
                                         unsigned a2, unsigned a3,
                                         unsigned b0, unsigned b1) {
    asm volatile("mma.sync.aligned.m16n8k16.row.col.f32.bf16.bf16.f32 "
        "{%0,%1,%2,%3}, {%4,%5,%6,%7}, {%8,%9}, {%0,%1,%2,%3};"
        : "+f"(c[0]), "+f"(c[1]), "+f"(c[2]), "+f"(c[3])
        : "r"(a0), "r"(a1), "r"(a2), "r"(a3), "r"(b0), "r"(b1));
}
#define CP_COMMIT asm volatile("cp.async.commit_group;" ::: "memory")
#define CP_WAIT1  asm volatile("cp.async.wait_group 1;" ::: "memory")
__device__ __forceinline__ void cpa16(unsigned dst, const void* src) {
    asm volatile("cp.async.cg.shared.global [%0], [%1], 16;" :: "r"(dst), "l"(src) : "memory");
}
__device__ __forceinline__ void cpcopy(unsigned sdst, const char* gsrc, int nbytes, int tid) {
    for (int i = tid*16; i < nbytes; i += 256*16) cpa16(sdst + i, gsrc + i);
}

// ---------------- kernel 1: projections ----------------
__global__ void __launch_bounds__(256, 2)
gat_proj_kernel(const float* __restrict__ h,
                const float* __restrict__ Ws,
                const float* __restrict__ Wt,
                const float* __restrict__ Wc) {
    __shared__ float shT[DIN*64];           // [k][r]
    const int r0 = blockIdx.x * 64;
    for (int idx = threadIdx.x; idx < 64*(DIN/4); idx += 256) {
        int k4 = idx >> 6, r = idx & 63;
        float4 v = *(const float4*)(h + (size_t)(r0 + r)*DIN + k4*4);
        shT[(k4*4+0)*64 + r] = v.x; shT[(k4*4+1)*64 + r] = v.y;
        shT[(k4*4+2)*64 + r] = v.z; shT[(k4*4+3)*64 + r] = v.w;
    }
    __syncthreads();
    const int t = threadIdx.x;
    const float* Wp; int stride, c, ostride; float* outp;
    if (t < 64)       { Wp = Ws; stride = DH; c = t;       outp = g_Whs; ostride = DH; }
    else if (t < 128) { Wp = Wt; stride = DH; c = t - 64;  outp = g_Wht; ostride = DH; }
    else              { Wp = Wc; stride = DO; c = t - 128; outp = g_Whc; ostride = DO; }
    float2 acc[32];
#pragma unroll
    for (int q = 0; q < 32; q++) acc[q] = make_float2(0.f, 0.f);
#pragma unroll 2
    for (int k = 0; k < DIN; k++) {
        float  w  = Wp[k*stride + c];
        float2 wp = make_float2(w, w);
        const float2* hp = (const float2*)(shT + k*64);
#pragma unroll
        for (int q = 0; q < 32; q++) acc[q] = ffma2(wp, hp[q], acc[q]);
    }
#pragma unroll
    for (int q = 0; q < 32; q++) {
        outp[(size_t)(r0 + 2*q    )*ostride + c] = acc[q].x;
        outp[(size_t)(r0 + 2*q + 1)*ostride + c] = acc[q].y;
    }
}

// ---------------- kernel 2: adjacency bitmask ----------------
__global__ void gat_pack_adj_kernel(const int* __restrict__ adj) {
    const int row = blockIdx.x, wi = threadIdx.x >> 5, lane = threadIdx.x & 31;
#pragma unroll 4
    for (int w = 0; w < 32; w++) {
        int word = wi*32 + w, col = word*32 + lane;
        unsigned bit = (adj[(size_t)row*N_ + col] > 0) ? 1u : 0u;
        unsigned m = __ballot_sync(0xffffffffu, bit);
        if (lane == 0) g_adjbits[row*NW + word] = m;
    }
}

// ---------------- kernel 3: split + swizzle images ----------------
// Q/K image: row r (0..127) x 64 bf16 = 128B rows; 16B seg s stored at s^(r&7).
// V image: row d=dout (0..127) x 128 keys bf16 = 256B rows; seg s (0..15) at s^(d&7).
__global__ void __launch_bounds__(256, 1) gat_pack_qkv() {
    extern __shared__ float sv[];            // [128][132] transposed Whc staging
    const int t = blockIdx.x, b = blockIdx.y, tid = threadIdx.x;
    const size_t nb = (size_t)b*N_ + (size_t)t*128;
    char* qb1 = (char*)(g_Q1 + ((size_t)b*NT + t)*8192);
    char* qb2 = (char*)(g_Q2 + ((size_t)b*NT + t)*8192);
    char* kb1 = (char*)(g_K1 + ((size_t)b*NT + t)*8192);
    char* kb2 = (char*)(g_K2 + ((size_t)b*NT + t)*8192);
    char* vb1 = (char*)(g_V1 + ((size_t)b*NT + t)*16384);
    char* vb2 = (char*)(g_V2 + ((size_t)b*NT + t)*16384);

    for (int i = tid; i < 1024; i += 256) {
        int r = i >> 3, s = i & 7;
        int off = r*128 + ((s ^ (r & 7)) << 4);
        uint4 u1, u2;
        {
            const float* src = g_Whs + (nb + r)*DH + 8*s;
            split2(src[0], src[1], u1.x, u2.x);
            split2(src[2], src[3], u1.y, u2.y);
            split2(src[4], src[5], u1.z, u2.z);
            split2(src[6], src[7], u1.w, u2.w);
            *(uint4*)(qb1 + off) = u1; *(uint4*)(qb2 + off) = u2;
        }
        {
            const float* src = g_Wht + (nb + r)*DH + 8*s;
            split2(src[0], src[1], u1.x, u2.x);
            split2(src[2], src[3], u1.y, u2.y);
            split2(src[4], src[5], u1.z, u2.z);
            split2(src[6], src[7], u1.w, u2.w);
            *(uint4*)(kb1 + off) = u1; *(uint4*)(kb2 + off) = u2;
        }
    }
    // stage Whc transposed: sv[dout][key]
    for (int i = tid; i < 4096; i += 256) {
        int k = i >> 5, d4 = i & 31;
        float4 v = *(const float4*)(g_Whc + (nb + k)*DO + 4*d4);
        sv[(4*d4+0)*132 + k] = v.x; sv[(4*d4+1)*132 + k] = v.y;
        sv[(4*d4+2)*132 + k] = v.z; sv[(4*d4+3)*132 + k] = v.w;
    }
    __syncthreads();
    for (int i = tid; i < 2048; i += 256) {
        int d = i >> 4, s = i & 15;
        const float* src = sv + d*132 + 8*s;
        uint4 u1, u2;
        split2(src[0], src[1], u1.x, u2.x);
        split2(src[2], src[3], u1.y, u2.y);
        split2(src[4], src[5], u1.z, u2.z);
        split2(src[6], src[7], u1.w, u2.w);
        int off = d*256 + ((s ^ (d & 7)) << 4);
        *(uint4*)(vb1 + off) = u1; *(uint4*)(vb2 + off) = u2;
    }
}

// ---------------- kernel 4: HMMA split-precision flash attention ----------------
// smem: Q 32KB | K bufs 2x32KB | V bufs 2x64KB  = 229376 B
#define SOFF_K 32768
#define SOFF_V 98304
#define SMEM_TOT 229376

__global__ void __launch_bounds__(256, 1)
gat_attn_kernel(float* __restrict__ out) {
    extern __shared__ char smc[];
    const unsigned sb = smem_u32(smc);
    const int qt = blockIdx.x, b = blockIdx.y;
    const int tid = threadIdx.x, lane = tid & 31, wid = tid >> 5;
    const int r0 = wid * 16;

    // ldmatrix lane geometry
    const unsigned q_row  = r0 + (lane & 15);
    const unsigned q_sel  = lane >> 4;
    const unsigned q_x7   = q_row & 7;
    const unsigned kv_r   = (lane & 7) | ((lane & 16) >> 1);   // 0..15
    const unsigned kv_sel = (lane >> 3) & 1;
    const unsigned kv_x7  = kv_r & 7;
    const unsigned sQrow  = sb + q_row*128;

    // ---- prologue async loads: group0 = Q + K(0) + V(0); group1 = K(1) + V(1)
    const size_t qoff = ((size_t)b*NT + qt)*8192;
    cpcopy(sb,          (const char*)(g_Q1 + qoff), 16384, tid);
    cpcopy(sb + 16384,  (const char*)(g_Q2 + qoff), 16384, tid);
    {
        size_t k0 = ((size_t)b*NT + 0);
        cpcopy(sb + SOFF_K,          (const char*)(g_K1 + k0*8192),  16384, tid);
        cpcopy(sb + SOFF_K + 16384,  (const char*)(g_K2 + k0*8192),  16384, tid);
        cpcopy(sb + SOFF_V,          (const char*)(g_V1 + k0*16384), 32768, tid);
        cpcopy(sb + SOFF_V + 32768,  (const char*)(g_V2 + k0*16384), 32768, tid);
    }
    CP_COMMIT;
    {
        size_t k1 = ((size_t)b*NT + 1);
        cpcopy(sb + SOFF_K + 32768,  (const char*)(g_K1 + k1*8192),  16384, tid);
        cpcopy(sb + SOFF_K + 49152,  (const char*)(g_K2 + k1*8192),  16384, tid);
        cpcopy(sb + SOFF_V + 65536,  (const char*)(g_V1 + k1*16384), 32768, tid);
        cpcopy(sb + SOFF_V + 98304,  (const char*)(g_V2 + k1*16384), 32768, tid);
    }
    CP_COMMIT;

    float o[16][4];
#pragma unroll
    for (int j = 0; j < 16; j++)
#pragma unroll
        for (int q = 0; q < 4; q++) o[j][q] = 0.f;
    float lA = 0.f, lB = 0.f;

    const int rAg = qt*128 + r0 + (lane >> 2);   // global query row for c0,c1
    const unsigned* adjA = g_adjbits + (size_t)rAg*NW;
    const unsigned* adjB = g_adjbits + (size_t)(rAg + 8)*NW;

    for (int t = 0; t < NT; t++) {
        CP_WAIT1;
        __syncthreads();
        const unsigned kb = sb + SOFF_K + (t & 1)*32768;
        const unsigned vb = sb + SOFF_V + (t & 1)*65536;

        // ---- S = Q@K^T : passes Q1K1 + Q2K1 + Q1K2, fp32 accum ----
        float s[16][4];
#pragma unroll
        for (int j = 0; j < 16; j++)
#pragma unroll
            for (int q = 0; q < 4; q++) s[j][q] = 0.f;
#pragma unroll
        for (int kk = 0; kk < 4; kk++) {
            unsigned a1[4], a2[4];
            unsigned qx = ((2*kk + q_sel) ^ q_x7) << 4;
            ldsm4(a1, sQrow + qx);
            ldsm4(a2, sQrow + 16384 + qx);
            unsigned kx = ((2*kk + kv_sel) ^ kv_x7) << 4;
#pragma unroll
            for (int jp = 0; jp < 8; jp++) {
                unsigned bf[4];
                unsigned ka = kb + kv_r*128 + jp*2048 + kx;
                ldsm4(bf, ka);                        // K1 (non-trans: rows = keys)
                mma16816(s[2*jp],   a1[0],a1[1],a1[2],a1[3], bf[0],bf[1]);
                mma16816(s[2*jp+1], a1[0],a1[1],a1[2],a1[3], bf[2],bf[3]);
                mma16816(s[2*jp],   a2[0],a2[1],a2[2],a2[3], bf[0],bf[1]);
                mma16816(s[2*jp+1], a2[0],a2[1],a2[2],a2[3], bf[2],bf[3]);
                ldsm4(bf, ka + 16384);                // K2
                mma16816(s[2*jp],   a1[0],a1[1],a1[2],a1[3], bf[0],bf[1]);
                mma16816(s[2*jp+1], a1[0],a1[1],a1[2],a1[3], bf[2],bf[3]);
            }
        }

        // ---- mask + exp(e-64) + bf16 split, all in registers ----
        unsigned mA0 = adjA[t*4+0], mA1 = adjA[t*4+1], mA2 = adjA[t*4+2], mA3 = adjA[t*4+3];
        unsigned mB0 = adjB[t*4+0], mB1 = adjB[t*4+1], mB2 = adjB[t*4+2], mB3 = adjB[t*4+3];
        unsigned p1lo[16], p1hi[16], p2lo[16], p2hi[16];
#pragma unroll
        for (int j = 0; j < 16; j++) {
            unsigned wa = (j < 4) ? mA0 : (j < 8) ? mA1 : (j < 12) ? mA2 : mA3;
            unsigned wb = (j < 4) ? mB0 : (j < 8) ? mB1 : (j < 12) ? mB2 : mB3;
            int bp = 8*(j & 3) + 2*(lane & 3);
            float pa0 = ((wa >> bp)     & 1u) ? ex2f(fmaf(s[j][0], LOG2E, -EXPC)) : 0.f;
            float pa1 = ((wa >> (bp+1)) & 1u) ? ex2f(fmaf(s[j][1], LOG2E, -EXPC)) : 0.f;
            float pb0 = ((wb >> bp)     & 1u) ? ex2f(fmaf(s[j][2], LOG2E, -EXPC)) : 0.f;
            float pb1 = ((wb >> (bp+1)) & 1u) ? ex2f(fmaf(s[j][3], LOG2E, -EXPC)) : 0.f;
            lA += pa0 + pa1;
            lB += pb0 + pb1;
            split2(pa0, pa1, p1lo[j], p2lo[j]);
            split2(pb0, pb1, p1hi[j], p2hi[j]);
        }

        // ---- O += P@V : passes P1V1 + P2V1 + P1V2 ----
#pragma unroll
        for (int kk = 0; kk < 8; kk++) {
            unsigned vx = ((2*kk + kv_sel) ^ kv_x7) << 4;
            unsigned a10 = p1lo[2*kk], a11 = p1hi[2*kk], a12 = p1lo[2*kk+1], a13 = p1hi[2*kk+1];
            unsigned a20 = p2lo[2*kk], a21 = p2hi[2*kk], a22 = p2lo[2*kk+1], a23 = p2hi[2*kk+1];
#pragma unroll
            for (int jp = 0; jp < 8; jp++) {
                unsigned bf[4];
                unsigned va = vb + kv_r*256 + jp*4096 + vx;
                ldsm4(bf, va);                        // V1 (image pre-transposed: rows = dout)
                mma16816(o[2*jp],   a10,a11,a12,a13, bf[0],bf[1]);
                mma16816(o[2*jp+1], a10,a11,a12,a13, bf[2],bf[3]);
                mma16816(o[2*jp],   a20,a21,a22,a23, bf[0],bf[1]);
                mma16816(o[2*jp+1], a20,a21,a22,a23, bf[2],bf[3]);
                ldsm4(bf, va + 32768);                // V2
                mma16816(o[2*jp],   a10,a11,a12,a13, bf[0],bf[1]);
                mma16816(o[2*jp+1], a10,a11,a12,a13, bf[2],bf[3]);
            }
        }

        __syncthreads();   // everyone done reading buf (t&1) before overwrite
        if (t + 2 < NT) {
            size_t kx = ((size_t)b*NT + t + 2);
            unsigned kd = sb + SOFF_K + (t & 1)*32768;
            unsigned vd = sb + SOFF_V + (t & 1)*65536;
            cpcopy(kd,          (const char*)(g_K1 + kx*8192),  16384, tid);
            cpcopy(kd + 16384,  (const char*)(g_K2 + kx*8192),  16384, tid);
            cpcopy(vd,          (const char*)(g_V1 + kx*16384), 32768, tid);
            cpcopy(vd + 32768,  (const char*)(g_V2 + kx*16384), 32768, tid);
        }
        CP_COMMIT;
    }

    // ---- epilogue: quad-reduce l, normalize, store ----
    lA += __shfl_xor_sync(0xffffffffu, lA, 1);
    lA += __shfl_xor_sync(0xffffffffu, lA, 2);
    lB += __shfl_xor_sync(0xffffffffu, lB, 1);
    lB += __shfl_xor_sync(0xffffffffu, lB, 2);
    float invA = 1.f / lA, invB = 1.f / lB;

    float* outA = out + ((size_t)b*N_ + rAg)*DO + 2*(lane & 3);
    float* outB = outA + 8*DO;
#pragma unroll
    for (int j = 0; j < 16; j++) {
        *(float2*)(outA + 8*j) = make_float2(o[j][0]*invA, o[j][1]*invA);
        *(float2*)(outB + 8*j) = make_float2(o[j][2]*invB, o[j][3]*invB);
    }
}

// ---------------- launch ----------------
extern "C" void kernel_launch(void* const* d_in, const int* in_sizes, int n_in,
                              void* d_out, int out_size) {
    const float* h   = (const float*)d_in[0];
    const int*   adj = (const int*)  d_in[1];
    const float* Ws  = (const float*)d_in[2];
    const float* Wt  = (const float*)d_in[3];
    const float* Wc  = (const float*)d_in[4];
    float* out = (float*)d_out;

    cudaFuncSetAttribute(gat_pack_qkv,
                         cudaFuncAttributeMaxDynamicSharedMemorySize, 128*132*4);
    cudaFuncSetAttribute(gat_attn_kernel,
                         cudaFuncAttributeMaxDynamicSharedMemorySize, SMEM_TOT);

    gat_proj_kernel<<<B_*N_/64, 256>>>(h, Ws, Wt, Wc);
    gat_pack_adj_kernel<<<N_, 128>>>(adj);
    gat_pack_qkv<<<dim3(NT, B_), 256, 128*132*4>>>();
    gat_attn_kernel<<<dim3(N_/TM, B_), 256, SMEM_TOT>>>(out);
}

// round 6
// speedup vs baseline: 2.9044x; 1.0574x over previous
#include <cuda_runtime.h>

#define B_   4
#define N_   4096
#define DIN  128
#define DH   64
#define DO   128
#define TM   128
#define TN   128
#define NT   (N_/TN)       // 32
#define NW   (N_/32)       // 128 mask words per row
#define LOG2E 1.4426950408889634f
#define EXPC  92.33248261689366f   /* 64 * log2(e) */

// ---------------- scratch ----------------
__device__ __align__(16) unsigned g_adjbits[N_*NW];
// pre-split, pre-swizzled bf16 images. Q/K: per (b,t) 128x64 bf16 (16KB).
// V: per (b,t) transposed 128(dout)x128(key) bf16 (32KB), 256B rows.
__device__ __align__(16) unsigned short g_Q1[B_*NT*8192];
__device__ __align__(16) unsigned short g_Q2[B_*NT*8192];
__device__ __align__(16) unsigned short g_K1[B_*NT*8192];
__device__ __align__(16) unsigned short g_K2[B_*NT*8192];
__device__ __align__(16) unsigned short g_V1[B_*NT*16384];
__device__ __align__(16) unsigned short g_V2[B_*NT*16384];

// ---------------- helpers ----------------
__device__ __forceinline__ unsigned smem_u32(const void* p) {
    unsigned a;
    asm("{ .reg .u64 t; cvta.to.shared.u64 t, %1; cvt.u32.u64 %0, t; }" : "=r"(a) : "l"(p));
    return a;
}
__device__ __forceinline__ float ex2f(float x) {
    float r; asm("ex2.approx.ftz.f32 %0, %1;" : "=f"(r) : "f"(x)); return r;
}
// split (a,b) into bf16x2 hi-part w1 and bf16x2 residual w2 (lo=a, hi=b)
__device__ __forceinline__ void split2(float a, float b, unsigned &w1, unsigned &w2) {
    unsigned hb;
    asm("cvt.rn.bf16x2.f32 %0, %1, %2;" : "=r"(hb) : "f"(b), "f"(a));
    float fa = __uint_as_float(hb << 16);
    float fb = __uint_as_float(hb & 0xffff0000u);
    asm("cvt.rn.bf16x2.f32 %0, %1, %2;" : "=r"(w2) : "f"(b - fb), "f"(a - fa));
    w1 = hb;
}
__device__ __forceinline__ float2 ffma2(float2 a, float2 b, float2 c) {
    unsigned long long ua = *reinterpret_cast<unsigned long long*>(&a);
    unsigned long long ub = *reinterpret_cast<unsigned long long*>(&b);
    unsigned long long uc = *reinterpret_cast<unsigned long long*>(&c);
    unsigned long long ud;
    asm("fma.rn.f32x2 %0, %1, %2, %3;" : "=l"(ud) : "l"(ua), "l"(ub), "l"(uc));
    return *reinterpret_cast<float2*>(&ud);
}
__device__ __forceinline__ void ldsm4(unsigned* r, unsigned addr) {
    asm volatile("ldmatrix.sync.aligned.m8n8.x4.shared.b16 {%0,%1,%2,%3}, [%4];"
        : "=r"(r[0]), "=r"(r[1]), "=r"(r[2]), "=r"(r[3]) : "r"(addr));
}
__device__ __forceinline__ void mma16816(float* c, unsigned a0, unsigned a1,
                                         unsigned a2, unsigned a3,
                                         unsigned b0, unsigned b1) {
    asm volatile("mma.sync.aligned.m16n8k16.row.col.f32.bf16.bf16.f32 "
        "{%0,%1,%2,%3}, {%4,%5,%6,%7}, {%8,%9}, {%0,%1,%2,%3};"
        : "+f"(c[0]), "+f"(c[1]), "+f"(c[2]), "+f"(c[3])
        : "r"(a0), "r"(a1), "r"(a2), "r"(a3), "r"(b0), "r"(b1));
}
#define CP_COMMIT asm volatile("cp.async.commit_group;" ::: "memory")
#define CP_WAIT1  asm volatile("cp.async.wait_group 1;" ::: "memory")
__device__ __forceinline__ void cpa16(unsigned dst, const void* src) {
    asm volatile("cp.async.cg.shared.global [%0], [%1], 16;" :: "r"(dst), "l"(src) : "memory");
}
__device__ __forceinline__ void cpcopy(unsigned sdst, const char* gsrc, int nbytes, int tid) {
    for (int i = tid*16; i < nbytes; i += 256*16) cpa16(sdst + i, gsrc + i);
}

// ---------------- kernel 1: fused projections + split + swizzle pack ----------------
// grid (NT, B_), 256 threads. Each CTA: one 128-row tile.
// smem: hT [128k][132] fp32 (h transposed), stage [256 cols][65] fp32 col-major.
#define HT_ST 132
#define ST_ST 65
#define PP_SMEM (128*HT_ST*4 + 256*ST_ST*4)

__global__ void __launch_bounds__(256, 1)
gat_proj_pack(const float* __restrict__ h,
              const float* __restrict__ Ws,
              const float* __restrict__ Wt,
              const float* __restrict__ Wc) {
    extern __shared__ float sm[];
    float* hT    = sm;
    float* stage = sm + 128*HT_ST;
    const int t = blockIdx.x, b = blockIdx.y, tid = threadIdx.x;
    const size_t nb = (size_t)b*N_ + (size_t)t*128;

    char* qb1 = (char*)(g_Q1 + ((size_t)b*NT + t)*8192);
    char* qb2 = (char*)(g_Q2 + ((size_t)b*NT + t)*8192);
    char* kb1 = (char*)(g_K1 + ((size_t)b*NT + t)*8192);
    char* kb2 = (char*)(g_K2 + ((size_t)b*NT + t)*8192);
    char* vb1 = (char*)(g_V1 + ((size_t)b*NT + t)*16384);
    char* vb2 = (char*)(g_V2 + ((size_t)b*NT + t)*16384);

    // load h transposed: hT[k][r], lanes vary r -> conflict-free smem writes
    for (int idx = tid; idx < 4096; idx += 256) {
        int r = idx & 127, k4 = idx >> 7;
        float4 v = *(const float4*)(h + (nb + r)*DIN + 4*k4);
        hT[(4*k4+0)*HT_ST + r] = v.x;
        hT[(4*k4+1)*HT_ST + r] = v.y;
        hT[(4*k4+2)*HT_ST + r] = v.z;
        hT[(4*k4+3)*HT_ST + r] = v.w;
    }
    __syncthreads();

    const float* Wp; int wstride, c;
    if (tid < 64)       { Wp = Ws; wstride = DH; c = tid; }
    else if (tid < 128) { Wp = Wt; wstride = DH; c = tid - 64; }
    else                { Wp = Wc; wstride = DO; c = tid - 128; }

#pragma unroll
    for (int pass = 0; pass < 2; pass++) {
        const int r0p = 64*pass;
        float2 acc[32];
#pragma unroll
        for (int q = 0; q < 32; q++) acc[q] = make_float2(0.f, 0.f);
#pragma unroll 4
        for (int k = 0; k < DIN; k++) {
            float w = Wp[k*wstride + c];
            float2 wp = make_float2(w, w);
            const float2* hp = (const float2*)(hT + k*HT_ST + r0p);
#pragma unroll
            for (int q = 0; q < 32; q++) acc[q] = ffma2(wp, hp[q], acc[q]);
        }
        __syncthreads();    // previous pass's pack reads done
        {
            float* stc = stage + tid*ST_ST;
#pragma unroll
            for (int q = 0; q < 32; q++) { stc[2*q] = acc[q].x; stc[2*q+1] = acc[q].y; }
        }
        __syncthreads();

        // Q/K images, rows r0p..r0p+63
        for (int i = tid; i < 512; i += 256) {
            int r = i >> 3, s = i & 7;
            int rr = r0p + r;
            int off = rr*128 + ((s ^ (rr & 7)) << 4);
            uint4 u1, u2;
            {
                const float* sc = stage + (8*s)*ST_ST + r;
                split2(sc[0*ST_ST], sc[1*ST_ST], u1.x, u2.x);
                split2(sc[2*ST_ST], sc[3*ST_ST], u1.y, u2.y);
                split2(sc[4*ST_ST], sc[5*ST_ST], u1.z, u2.z);
                split2(sc[6*ST_ST], sc[7*ST_ST], u1.w, u2.w);
                *(uint4*)(qb1 + off) = u1; *(uint4*)(qb2 + off) = u2;
            }
            {
                const float* sc = stage + (64 + 8*s)*ST_ST + r;
                split2(sc[0*ST_ST], sc[1*ST_ST], u1.x, u2.x);
                split2(sc[2*ST_ST], sc[3*ST_ST], u1.y, u2.y);
                split2(sc[4*ST_ST], sc[5*ST_ST], u1.z, u2.z);
                split2(sc[6*ST_ST], sc[7*ST_ST], u1.w, u2.w);
                *(uint4*)(kb1 + off) = u1; *(uint4*)(kb2 + off) = u2;
            }
        }
        // V image (transposed [dout][key]): this pass covers keys r0p..r0p+63
        for (int i = tid; i < 1024; i += 256) {
            int d = i & 127, sh = i >> 7;            // sh 0..7 -> 8 keys each
            int sg = (r0p >> 3) + sh;                // global 16B segment 0..15
            const float* sc = stage + (128 + d)*ST_ST + 8*sh;
            uint4 u1, u2;
            split2(sc[0], sc[1], u1.x, u2.x);
            split2(sc[2], sc[3], u1.y, u2.y);
            split2(sc[4], sc[5], u1.z, u2.z);
            split2(sc[6], sc[7], u1.w, u2.w);
            int off = d*256 + ((sg ^ (d & 7)) << 4);
            *(uint4*)(vb1 + off) = u1; *(uint4*)(vb2 + off) = u2;
        }
    }
}

// ---------------- kernel 2: adjacency bitmask ----------------
__global__ void gat_pack_adj_kernel(const int* __restrict__ adj) {
    const int row = blockIdx.x, wi = threadIdx.x >> 5, lane = threadIdx.x & 31;
#pragma unroll 4
    for (int w = 0; w < 32; w++) {
        int word = wi*32 + w, col = word*32 + lane;
        unsigned bit = (adj[(size_t)row*N_ + col] > 0) ? 1u : 0u;
        unsigned m = __ballot_sync(0xffffffffu, bit);
        if (lane == 0) g_adjbits[row*NW + word] = m;
    }
}

// ---------------- kernel 3: HMMA split-precision flash attention ----------------
// smem: Q 32KB | K bufs 2x32KB | V bufs 2x64KB  = 229376 B
#define SOFF_K 32768
#define SOFF_V 98304
#define SMEM_TOT 229376

__global__ void __launch_bounds__(256, 1)
gat_attn_kernel(float* __restrict__ out) {
    extern __shared__ char smc[];
    const unsigned sb = smem_u32(smc);
    const int qt = blockIdx.x, b = blockIdx.y;
    const int tid = threadIdx.x, lane = tid & 31, wid = tid >> 5;
    const int r0 = wid * 16;

    // ldmatrix lane geometry
    const unsigned q_row  = r0 + (lane & 15);
    const unsigned q_sel  = lane >> 4;
    const unsigned q_x7   = q_row & 7;
    const unsigned kv_r   = (lane & 7) | ((lane & 16) >> 1);   // 0..15
    const unsigned kv_sel = (lane >> 3) & 1;
    const unsigned kv_x7  = kv_r & 7;
    const unsigned sQrow  = sb + q_row*128;

    // ---- prologue async loads: group0 = Q + K(0) + V(0); group1 = K(1) + V(1)
    const size_t qoff = ((size_t)b*NT + qt)*8192;
    cpcopy(sb,          (const char*)(g_Q1 + qoff), 16384, tid);
    cpcopy(sb + 16384,  (const char*)(g_Q2 + qoff), 16384, tid);
    {
        size_t k0 = ((size_t)b*NT + 0);
        cpcopy(sb + SOFF_K,          (const char*)(g_K1 + k0*8192),  16384, tid);
        cpcopy(sb + SOFF_K + 16384,  (const char*)(g_K2 + k0*8192),  16384, tid);
        cpcopy(sb + SOFF_V,          (const char*)(g_V1 + k0*16384), 32768, tid);
        cpcopy(sb + SOFF_V + 32768,  (const char*)(g_V2 + k0*16384), 32768, tid);
    }
    CP_COMMIT;
    {
        size_t k1 = ((size_t)b*NT + 1);
        cpcopy(sb + SOFF_K + 32768,  (const char*)(g_K1 + k1*8192),  16384, tid);
        cpcopy(sb + SOFF_K + 49152,  (const char*)(g_K2 + k1*8192),  16384, tid);
        cpcopy(sb + SOFF_V + 65536,  (const char*)(g_V1 + k1*16384), 32768, tid);
        cpcopy(sb + SOFF_V + 98304,  (const char*)(g_V2 + k1*16384), 32768, tid);
    }
    CP_COMMIT;

    float o[16][4];
#pragma unroll
    for (int j = 0; j < 16; j++)
#pragma unroll
        for (int q = 0; q < 4; q++) o[j][q] = 0.f;
    float lA = 0.f, lB = 0.f;

    const int rAg = qt*128 + r0 + (lane >> 2);   // global query row for c0,c1
    const unsigned* adjA = g_adjbits + (size_t)rAg*NW;
    const unsigned* adjB = g_adjbits + (size_t)(rAg + 8)*NW;

    for (int t = 0; t < NT; t++) {
        CP_WAIT1;
        __syncthreads();
        const unsigned kb = sb + SOFF_K + (t & 1)*32768;
        const unsigned vb = sb + SOFF_V + (t & 1)*65536;

        float s[16][4];
#pragma unroll
        for (int j = 0; j < 16; j++)
#pragma unroll
            for (int q = 0; q < 4; q++) s[j][q] = 0.f;

        unsigned mA0 = adjA[t*4+0], mA1 = adjA[t*4+1], mA2 = adjA[t*4+2], mA3 = adjA[t*4+3];
        unsigned mB0 = adjB[t*4+0], mB1 = adjB[t*4+1], mB2 = adjB[t*4+2], mB3 = adjB[t*4+3];
        unsigned p1lo[16], p1hi[16], p2lo[16], p2hi[16];

        // softmax for one n8-chunk j: mask + exp + bf16 split
        auto softmax_j = [&](int j) {
            unsigned wa = (j < 4) ? mA0 : (j < 8) ? mA1 : (j < 12) ? mA2 : mA3;
            unsigned wb = (j < 4) ? mB0 : (j < 8) ? mB1 : (j < 12) ? mB2 : mB3;
            int bp = 8*(j & 3) + 2*(lane & 3);
            float pa0 = ((wa >> bp)     & 1u) ? ex2f(fmaf(s[j][0], LOG2E, -EXPC)) : 0.f;
            float pa1 = ((wa >> (bp+1)) & 1u) ? ex2f(fmaf(s[j][1], LOG2E, -EXPC)) : 0.f;
            float pb0 = ((wb >> bp)     & 1u) ? ex2f(fmaf(s[j][2], LOG2E, -EXPC)) : 0.f;
            float pb1 = ((wb >> (bp+1)) & 1u) ? ex2f(fmaf(s[j][3], LOG2E, -EXPC)) : 0.f;
            lA += pa0 + pa1;
            lB += pb0 + pb1;
            split2(pa0, pa1, p1lo[j], p2lo[j]);
            split2(pb0, pb1, p1hi[j], p2hi[j]);
        };
        // PV body for one 16-key chunk kk
        auto pv_kk = [&](int kk) {
            unsigned vx = ((2*kk + kv_sel) ^ kv_x7) << 4;
            unsigned a10 = p1lo[2*kk], a11 = p1hi[2*kk], a12 = p1lo[2*kk+1], a13 = p1hi[2*kk+1];
            unsigned a20 = p2lo[2*kk], a21 = p2hi[2*kk], a22 = p2lo[2*kk+1], a23 = p2hi[2*kk+1];
#pragma unroll
            for (int jp = 0; jp < 8; jp++) {
                unsigned bf[4];
                unsigned va = vb + kv_r*256 + jp*4096 + vx;
                ldsm4(bf, va);                        // V1 (rows = dout, pre-transposed)
                mma16816(o[2*jp],   a10,a11,a12,a13, bf[0],bf[1]);
                mma16816(o[2*jp+1], a10,a11,a12,a13, bf[2],bf[3]);
                mma16816(o[2*jp],   a20,a21,a22,a23, bf[0],bf[1]);
                mma16816(o[2*jp+1], a20,a21,a22,a23, bf[2],bf[3]);
                ldsm4(bf, va + 32768);                // V2
                mma16816(o[2*jp],   a10,a11,a12,a13, bf[0],bf[1]);
                mma16816(o[2*jp+1], a10,a11,a12,a13, bf[2],bf[3]);
            }
        };

        // ---- QK half 0: key chunks jp 0..3 (all dh) ----
#pragma unroll
        for (int kk = 0; kk < 4; kk++) {
            unsigned a1[4], a2[4];
            unsigned qx = ((2*kk + q_sel) ^ q_x7) << 4;
            ldsm4(a1, sQrow + qx);
            ldsm4(a2, sQrow + 16384 + qx);
            unsigned kx = ((2*kk + kv_sel) ^ kv_x7) << 4;
#pragma unroll
            for (int jp = 0; jp < 4; jp++) {
                unsigned bf[4];
                unsigned ka = kb + kv_r*128 + jp*2048 + kx;
                ldsm4(bf, ka);                        // K1
                mma16816(s[2*jp],   a1[0],a1[1],a1[2],a1[3], bf[0],bf[1]);
                mma16816(s[2*jp+1], a1[0],a1[1],a1[2],a1[3], bf[2],bf[3]);
                mma16816(s[2*jp],   a2[0],a2[1],a2[2],a2[3], bf[0],bf[1]);
                mma16816(s[2*jp+1], a2[0],a2[1],a2[2],a2[3], bf[2],bf[3]);
                ldsm4(bf, ka + 16384);                // K2
                mma16816(s[2*jp],   a1[0],a1[1],a1[2],a1[3], bf[0],bf[1]);
                mma16816(s[2*jp+1], a1[0],a1[1],a1[2],a1[3], bf[2],bf[3]);
            }
        }
        // ---- QK half 1 (jp 4..7) interleaved with softmax of half 0 ----
#pragma unroll
        for (int kk = 0; kk < 4; kk++) {
            unsigned a1[4], a2[4];
            unsigned qx = ((2*kk + q_sel) ^ q_x7) << 4;
            ldsm4(a1, sQrow + qx);
            ldsm4(a2, sQrow + 16384 + qx);
            unsigned kx = ((2*kk + kv_sel) ^ kv_x7) << 4;
#pragma unroll
            for (int jp = 4; jp < 8; jp++) {
                unsigned bf[4];
                unsigned ka = kb + kv_r*128 + jp*2048 + kx;
                ldsm4(bf, ka);
                mma16816(s[2*jp],   a1[0],a1[1],a1[2],a1[3], bf[0],bf[1]);
                mma16816(s[2*jp+1], a1[0],a1[1],a1[2],a1[3], bf[2],bf[3]);
                mma16816(s[2*jp],   a2[0],a2[1],a2[2],a2[3], bf[0],bf[1]);
                mma16816(s[2*jp+1], a2[0],a2[1],a2[2],a2[3], bf[2],bf[3]);
                ldsm4(bf, ka + 16384);
                mma16816(s[2*jp],   a1[0],a1[1],a1[2],a1[3], bf[0],bf[1]);
                mma16816(s[2*jp+1], a1[0],a1[1],a1[2],a1[3], bf[2],bf[3]);
            }
            softmax_j(2*kk);
            softmax_j(2*kk + 1);
        }
        // ---- PV half 0 (keys 0..63) interleaved with softmax of half 1 ----
#pragma unroll
        for (int kk = 0; kk < 4; kk++) {
            softmax_j(8 + 2*kk);
            softmax_j(9 + 2*kk);
            pv_kk(kk);
        }
        // ---- PV half 1 (keys 64..127) ----
#pragma unroll
        for (int kk = 4; kk < 8; kk++) pv_kk(kk);

        __syncthreads();   // everyone done reading buf (t&1) before overwrite
        if (t + 2 < NT) {
            size_t kx = ((size_t)b*NT + t + 2);
            unsigned kd = sb + SOFF_K + (t & 1)*32768;
            unsigned vd = sb + SOFF_V + (t & 1)*65536;
            cpcopy(kd,          (const char*)(g_K1 + kx*8192),  16384, tid);
            cpcopy(kd + 16384,  (const char*)(g_K2 + kx*8192),  16384, tid);
            cpcopy(vd,          (const char*)(g_V1 + kx*16384), 32768, tid);
            cpcopy(vd + 32768,  (const char*)(g_V2 + kx*16384), 32768, tid);
        }
        CP_COMMIT;
    }

    // ---- epilogue: quad-reduce l, normalize, store ----
    lA += __shfl_xor_sync(0xffffffffu, lA, 1);
    lA += __shfl_xor_sync(0xffffffffu, lA, 2);
    lB += __shfl_xor_sync(0xffffffffu, lB, 1);
    lB += __shfl_xor_sync(0xffffffffu, lB, 2);
    float invA = 1.f / lA, invB = 1.f / lB;

    float* outA = out + ((size_t)b*N_ + rAg)*DO + 2*(lane & 3);
    float* outB = outA + 8*DO;
#pragma unroll
    for (int j = 0; j < 16; j++) {
        *(float2*)(outA + 8*j) = make_float2(o[j][0]*invA, o[j][1]*invA);
        *(float2*)(outB + 8*j) = make_float2(o[j][2]*invB, o[j][3]*invB);
    }
}

// ---------------- launch ----------------
extern "C" void kernel_launch(void* const* d_in, const int* in_sizes, int n_in,
                              void* d_out, int out_size) {
    const float* h   = (const float*)d_in[0];
    const int*   adj = (const int*)  d_in[1];
    const float* Ws  = (const float*)d_in[2];
    const float* Wt  = (const float*)d_in[3];
    const float* Wc  = (const float*)d_in[4];
    float* out = (float*)d_out;

    cudaFuncSetAttribute(gat_proj_pack,
                         cudaFuncAttributeMaxDynamicSharedMemorySize, PP_SMEM);
    cudaFuncSetAttribute(gat_attn_kernel,
                         cudaFuncAttributeMaxDynamicSharedMemorySize, SMEM_TOT);

    gat_proj_pack<<<dim3(NT, B_), 256, PP_SMEM>>>(h, Ws, Wt, Wc);
    gat_pack_adj_kernel<<<N_, 128>>>(adj);
    gat_attn_kernel<<<dim3(N_/TM, B_), 256, SMEM_TOT>>>(out);
}